// round 5
// baseline (speedup 1.0000x reference)
#include <cuda_runtime.h>

#define NMAX 100000
#define EMAX 1600000
#define DV 128

typedef unsigned long long ull;

// Scratch (device globals — allocation-free per harness rules)
__device__ float g_H[NMAX * DV];      // node features (post-layer)
__device__ float g_M[NMAX * DV];      // messages: (h @ W) * dinv[row]
__device__ float g_dinv[NMAX];
__device__ int   g_deg[NMAX];
__device__ int   g_cur[NMAX];
__device__ int   g_rptr[NMAX + 1];
__device__ int   g_col[EMAX];
__device__ int   g_src[EMAX];
__device__ int   g_dst[EMAX];
__device__ int   g_batch[NMAX];
__device__ int   g_is64;

// ---------------- dtype probe: int64 vs int32 index buffers ----------------
__global__ void k_detect(const void* edge, int E) {
    const long long* e64 = (const long long*)edge;
    int ok = 1;
    for (int i = 0; i < 8; i++) {
        long long v = e64[i];
        if (v < 0 || v >= (1LL << 31)) ok = 0;
    }
    g_is64 = ok;
}

// ---------------- normalize edge + batch to int32 ----------------
__global__ void k_cvt_edge(const void* edge, int E) {
    int i = blockIdx.x * blockDim.x + threadIdx.x;
    if (i >= E) return;
    int s, d;
    if (g_is64) {
        const long long* e = (const long long*)edge;
        s = (int)e[i];
        d = (int)e[E + i];
    } else {
        const int* e = (const int*)edge;
        s = e[i];
        d = e[E + i];
    }
    g_src[i] = s;
    g_dst[i] = d;
}

__global__ void k_cvt_batch(const void* batch, int N) {
    int i = blockIdx.x * blockDim.x + threadIdx.x;
    if (i >= N) return;
    g_batch[i] = g_is64 ? (int)((const long long*)batch)[i]
                        : ((const int*)batch)[i];
}

// ---------------- zero counters ----------------
__global__ void k_zero(int N) {
    int i = blockIdx.x * blockDim.x + threadIdx.x;
    if (i < N) { g_deg[i] = 0; g_cur[i] = 0; }
}

// ---------------- degree histogram on dst (clamped: trap-proof) ----------------
__global__ void k_deg(int E, int N) {
    int i = blockIdx.x * blockDim.x + threadIdx.x;
    if (i >= E) return;
    unsigned d = (unsigned)g_dst[i];
    if (d < (unsigned)N) atomicAdd(&g_deg[d], 1);
}

__global__ void k_dinv(int N) {
    int i = blockIdx.x * blockDim.x + threadIdx.x;
    if (i < N) g_dinv[i] = rsqrtf((float)(g_deg[i] + 1));   // +1 self-loop
}

// ---------------- exclusive scan -> g_rptr (single block, 1024 thr) ----------------
__global__ void __launch_bounds__(1024) k_scan(int N) {
    __shared__ int ssum[1024];
    int t = threadIdx.x;
    int per = (N + 1023) / 1024;
    int begin = t * per;
    int end   = begin + per; if (end > N) end = N; if (begin > N) begin = N;
    int s = 0;
    for (int i = begin; i < end; i++) s += g_deg[i];
    ssum[t] = s;
    __syncthreads();
    for (int off = 1; off < 1024; off <<= 1) {
        int v = (t >= off) ? ssum[t - off] : 0;
        __syncthreads();
        ssum[t] += v;
        __syncthreads();
    }
    int run = (t == 0) ? 0 : ssum[t - 1];
    for (int i = begin; i < end; i++) { g_rptr[i] = run; run += g_deg[i]; }
    if (t == 1023) g_rptr[N] = run;
}

// ---------------- CSR fill: bucket src indices by dst (clamped) ----------------
__global__ void k_fill(int E, int N) {
    int i = blockIdx.x * blockDim.x + threadIdx.x;
    if (i >= E) return;
    unsigned d = (unsigned)g_dst[i];
    unsigned s = (unsigned)g_src[i];
    if (d >= (unsigned)N || s >= (unsigned)N) return;
    int pos = atomicAdd(&g_cur[d], 1);
    g_col[g_rptr[d] + pos] = (int)s;
}

// ---------------- GEMM: M = (Hin @ W) * dinv[row]  (f32x2 packed FMA) ----------------
__device__ __forceinline__ ull dup32(float x) {
    ull u = (ull)__float_as_uint(x);
    return (u << 32) | u;
}

__global__ void __launch_bounds__(256) k_gemm(const float* __restrict__ xin,
                                              const float* __restrict__ W,
                                              int N, int useH) {
    const float* __restrict__ Hin = useH ? (const float*)g_H : xin;
    __shared__ float Ws[32][128];   // 16 KB: 32 K-rows of W
    __shared__ ull   Hs2[64][32];   // 16 KB: 64 M-rows x 32 K, each value duplicated {x,x}

    int tid  = threadIdx.x;
    int row0 = blockIdx.x * 64;
    int tx   = tid & 15;   // 16 col-groups of 8 output cols (4 f32x2 pairs)
    int ty   = tid >> 4;   // 16 row-groups of 4 rows

    ull acc[4][4];
#pragma unroll
    for (int r = 0; r < 4; r++)
#pragma unroll
        for (int p = 0; p < 4; p++) acc[r][p] = 0ull;

    for (int kk = 0; kk < 128; kk += 32) {
        __syncthreads();
        // stage W rows kk..kk+31 : 1024 float4
        const float4* W4  = (const float4*)(W + (size_t)kk * 128);
        float4*       Ws4 = (float4*)&Ws[0][0];
#pragma unroll
        for (int i = 0; i < 4; i++) Ws4[tid + i * 256] = W4[tid + i * 256];
        // stage H tile rows [row0, row0+64), k in [kk, kk+32), duplicated pairs : 512 float4
#pragma unroll
        for (int i = 0; i < 2; i++) {
            int j   = tid + i * 256;       // 0..511
            int row = j >> 3;              // 8 float4 per row
            int c4  = j & 7;
            float4 v = make_float4(0.f, 0.f, 0.f, 0.f);
            if (row0 + row < N)
                v = ((const float4*)(Hin + (size_t)(row0 + row) * 128 + kk))[c4];
            ull* hp = &Hs2[row][c4 * 4];
            hp[0] = dup32(v.x); hp[1] = dup32(v.y);
            hp[2] = dup32(v.z); hp[3] = dup32(v.w);
        }
        __syncthreads();

#pragma unroll
        for (int k = 0; k < 32; k += 2) {
            const ull* wr0 = (const ull*)&Ws[k][tx * 8];
            const ull* wr1 = (const ull*)&Ws[k + 1][tx * 8];
            ull w00 = wr0[0], w01 = wr0[1], w02 = wr0[2], w03 = wr0[3];
            ull w10 = wr1[0], w11 = wr1[1], w12 = wr1[2], w13 = wr1[3];
#pragma unroll
            for (int r = 0; r < 4; r++) {
                ulonglong2 a = *(const ulonglong2*)&Hs2[ty * 4 + r][k];
                asm("fma.rn.f32x2 %0, %1, %2, %0;" : "+l"(acc[r][0]) : "l"(a.x), "l"(w00));
                asm("fma.rn.f32x2 %0, %1, %2, %0;" : "+l"(acc[r][1]) : "l"(a.x), "l"(w01));
                asm("fma.rn.f32x2 %0, %1, %2, %0;" : "+l"(acc[r][2]) : "l"(a.x), "l"(w02));
                asm("fma.rn.f32x2 %0, %1, %2, %0;" : "+l"(acc[r][3]) : "l"(a.x), "l"(w03));
                asm("fma.rn.f32x2 %0, %1, %2, %0;" : "+l"(acc[r][0]) : "l"(a.y), "l"(w10));
                asm("fma.rn.f32x2 %0, %1, %2, %0;" : "+l"(acc[r][1]) : "l"(a.y), "l"(w11));
                asm("fma.rn.f32x2 %0, %1, %2, %0;" : "+l"(acc[r][2]) : "l"(a.y), "l"(w12));
                asm("fma.rn.f32x2 %0, %1, %2, %0;" : "+l"(acc[r][3]) : "l"(a.y), "l"(w13));
            }
        }
    }

    // epilogue: M[row] = acc * dinv[row]   (f32x2 pair = two adjacent output cols)
#pragma unroll
    for (int r = 0; r < 4; r++) {
        int row = row0 + ty * 4 + r;
        if (row >= N) continue;
        float dv = g_dinv[row];
        float2* Mp = (float2*)(g_M + (size_t)row * 128 + tx * 8);
#pragma unroll
        for (int p = 0; p < 4; p++) {
            float2 v = *(float2*)&acc[r][p];
            Mp[p] = make_float2(v.x * dv, v.y * dv);
        }
    }
}

// ---------------- gather aggregation + bias + relu ----------------
// H[d] = relu( dinv[d] * ( M[d] + sum_{e: dst=d} M[src_e] ) + b )
__global__ void __launch_bounds__(256) k_gather(const float* __restrict__ b, int N) {
    int w = (blockIdx.x * 256 + threadIdx.x) >> 5;
    if (w >= N) return;
    int lane = threadIdx.x & 31;

    int s0 = g_rptr[w], s1 = g_rptr[w + 1];
    float dv = g_dinv[w];
    const float4* M4 = (const float4*)g_M;

    float4 acc = M4[(size_t)w * 32 + lane];   // self-loop message (pre-scaled by dinv[w])

    int e = s0;
    for (; e + 3 < s1; e += 4) {
        int sa = g_col[e], sb = g_col[e + 1], sc = g_col[e + 2], sd = g_col[e + 3];
        float4 va = M4[(size_t)sa * 32 + lane];
        float4 vb = M4[(size_t)sb * 32 + lane];
        float4 vc = M4[(size_t)sc * 32 + lane];
        float4 vd = M4[(size_t)sd * 32 + lane];
        acc.x += va.x + vb.x + vc.x + vd.x;
        acc.y += va.y + vb.y + vc.y + vd.y;
        acc.z += va.z + vb.z + vc.z + vd.z;
        acc.w += va.w + vb.w + vc.w + vd.w;
    }
    for (; e < s1; e++) {
        int s = g_col[e];
        float4 v = M4[(size_t)s * 32 + lane];
        acc.x += v.x; acc.y += v.y; acc.z += v.z; acc.w += v.w;
    }

    float4 bb = ((const float4*)b)[lane];
    float4 o;
    o.x = fmaxf(acc.x * dv + bb.x, 0.f);
    o.y = fmaxf(acc.y * dv + bb.y, 0.f);
    o.z = fmaxf(acc.z * dv + bb.z, 0.f);
    o.w = fmaxf(acc.w * dv + bb.w, 0.f);
    ((float4*)g_H)[(size_t)w * 32 + lane] = o;
}

// ---------------- fused pooling (max/mean/sum) + output linear (no atomics) ----------------
__global__ void __launch_bounds__(128) k_pool_out(const float* __restrict__ out_w,
                                                  const float* __restrict__ out_b,
                                                  float* __restrict__ out, int N) {
    int g = blockIdx.x;    // 256 graphs
    int d = threadIdx.x;   // 128 dims

    // g_batch is sorted: binary search segment [lo, hi)
    int lo, hi;
    { int a = 0, b = N; while (a < b) { int m = (a + b) >> 1; if (g_batch[m] < g) a = m + 1; else b = m; } lo = a; }
    { int a = lo, b = N; while (a < b) { int m = (a + b) >> 1; if (g_batch[m] < g + 1) a = m + 1; else b = m; } hi = a; }

    float s = 0.f, mx = 0.f;   // relu output >= 0, so max init 0 matches segment_max for non-empty segments
    for (int n = lo; n < hi; n++) {
        float v = g_H[(size_t)n * 128 + d];
        s += v;
        mx = fmaxf(mx, v);
    }
    float cnt  = fmaxf((float)(hi - lo), 1.f);
    float mean = s / cnt;

    __shared__ float sp[128][10];
#pragma unroll
    for (int j = 0; j < 10; j++)
        sp[d][j] = mx * out_w[d * 10 + j]
                 + mean * out_w[(128 + d) * 10 + j]
                 + s * out_w[(256 + d) * 10 + j];
    __syncthreads();

    if (d < 10) {
        float r = 0.f;
        for (int i = 0; i < 128; i++) r += sp[i][d];
        out[g * 10 + d] = r + out_b[d];
    }
}

// ---------------- launch ----------------
extern "C" void kernel_launch(void* const* d_in, const int* in_sizes, int n_in,
                              void* d_out, int out_size) {
    const float* x      = (const float*)d_in[0];
    const void*  edge   = d_in[1];
    const void*  batch  = d_in[2];
    const float* conv_w = (const float*)d_in[3];
    const float* conv_b = (const float*)d_in[4];
    const float* out_w  = (const float*)d_in[5];
    const float* out_b  = (const float*)d_in[6];
    float*       out    = (float*)d_out;

    int N = in_sizes[0] / 128;
    int E = in_sizes[1] / 2;

    k_detect<<<1, 1>>>(edge, E);
    k_cvt_edge<<<(E + 255) / 256, 256>>>(edge, E);
    k_cvt_batch<<<(N + 255) / 256, 256>>>(batch, N);

    k_zero<<<(N + 255) / 256, 256>>>(N);
    k_deg<<<(E + 255) / 256, 256>>>(E, N);
    k_dinv<<<(N + 255) / 256, 256>>>(N);
    k_scan<<<1, 1024>>>(N);
    k_fill<<<(E + 255) / 256, 256>>>(E, N);

    for (int l = 0; l < 3; l++) {
        k_gemm<<<(N + 63) / 64, 256>>>(x, conv_w + (size_t)l * 128 * 128, N, l > 0 ? 1 : 0);
        k_gather<<<(N * 32 + 255) / 256, 256>>>(conv_b + l * 128, N);
    }

    k_pool_out<<<256, 128>>>(out_w, out_b, out, N);
}

// round 7
// speedup vs baseline: 1.4097x; 1.4097x over previous
#include <cuda_runtime.h>
#include <cuda_bf16.h>
#include <cstdint>

#define NMAX 100000
#define EMAX 1600000

// Scratch (device globals — allocation-free per harness rules)
__device__ float g_H[NMAX * 128];     // node features (post-layer)
__device__ float g_M[NMAX * 128];     // messages: (h @ W) * dinv[row]
__device__ float g_dinv[NMAX];
__device__ int   g_deg[NMAX];
__device__ int   g_cur[NMAX];
__device__ int   g_rptr[NMAX + 1];
__device__ int   g_col[EMAX];
__device__ int   g_src[EMAX];
__device__ int   g_dst[EMAX];
__device__ int   g_batch[NMAX];
__device__ int   g_is64;

// Pre-converted bf16 W images, B-layout [n][k] with rows padded to 136 halves.
// g_Wb[layer][hi/lo][n*136 + k]
#define BROW 136
__device__ __align__(16) unsigned short g_Wb[3][2][128 * BROW];

__device__ __forceinline__ uint32_t packbf(float x0, float x1) {
    return ((uint32_t)__bfloat16_as_ushort(__float2bfloat16(x1)) << 16)
         |  (uint32_t)__bfloat16_as_ushort(__float2bfloat16(x0));
}

// ===================== dtype probe / index normalization =====================
__global__ void k_detect(const void* edge, int E) {
    const long long* e64 = (const long long*)edge;
    int ok = 1;
    for (int i = 0; i < 8; i++) {
        long long v = e64[i];
        if (v < 0 || v >= (1LL << 31)) ok = 0;
    }
    g_is64 = ok;
}

__global__ void k_cvt_edge(const void* edge, int E) {
    int i = blockIdx.x * blockDim.x + threadIdx.x;
    if (i >= E) return;
    int s, d;
    if (g_is64) {
        const long long* e = (const long long*)edge;
        s = (int)e[i];
        d = (int)e[E + i];
    } else {
        const int* e = (const int*)edge;
        s = e[i];
        d = e[E + i];
    }
    g_src[i] = s;
    g_dst[i] = d;
}

__global__ void k_cvt_batch(const void* batch, int N) {
    int i = blockIdx.x * blockDim.x + threadIdx.x;
    if (i >= N) return;
    g_batch[i] = g_is64 ? (int)((const long long*)batch)[i]
                        : ((const int*)batch)[i];
}

// ===================== CSR build =====================
__global__ void k_zero(int N) {
    int i = blockIdx.x * blockDim.x + threadIdx.x;
    if (i < N) { g_deg[i] = 0; g_cur[i] = 0; }
}

__global__ void k_deg(int E, int N) {
    int i = blockIdx.x * blockDim.x + threadIdx.x;
    if (i >= E) return;
    unsigned d = (unsigned)g_dst[i];
    if (d < (unsigned)N) atomicAdd(&g_deg[d], 1);
}

__global__ void k_dinv(int N) {
    int i = blockIdx.x * blockDim.x + threadIdx.x;
    if (i < N) g_dinv[i] = rsqrtf((float)(g_deg[i] + 1));   // +1 self-loop
}

__global__ void __launch_bounds__(1024) k_scan(int N) {
    __shared__ int ssum[1024];
    int t = threadIdx.x;
    int per = (N + 1023) / 1024;
    int begin = t * per;
    int end   = begin + per; if (end > N) end = N; if (begin > N) begin = N;
    int s = 0;
    for (int i = begin; i < end; i++) s += g_deg[i];
    ssum[t] = s;
    __syncthreads();
    for (int off = 1; off < 1024; off <<= 1) {
        int v = (t >= off) ? ssum[t - off] : 0;
        __syncthreads();
        ssum[t] += v;
        __syncthreads();
    }
    int run = (t == 0) ? 0 : ssum[t - 1];
    for (int i = begin; i < end; i++) { g_rptr[i] = run; run += g_deg[i]; }
    if (t == 1023) g_rptr[N] = run;
}

__global__ void k_fill(int E, int N) {
    int i = blockIdx.x * blockDim.x + threadIdx.x;
    if (i >= E) return;
    unsigned d = (unsigned)g_dst[i];
    unsigned s = (unsigned)g_src[i];
    if (d >= (unsigned)N || s >= (unsigned)N) return;
    int pos = atomicAdd(&g_cur[d], 1);
    g_col[g_rptr[d] + pos] = (int)s;
}

// ===================== W -> bf16 hi/lo images in B layout [n][k] =====================
// B[n][k] = W[k][n]. Grid (16 k-groups, 3 layers), 128 threads = n.
__global__ void k_wconv(const float* __restrict__ conv_w) {
    int l = blockIdx.y;
    int c = blockIdx.x * 8;    // k group of 8
    int n = threadIdx.x;       // 0..127
    const float* W = conv_w + (size_t)l * 16384;
    uint32_t hi[4], lo[4];
#pragma unroll
    for (int j = 0; j < 4; j++) {
        float v0 = W[(size_t)(c + 2 * j) * 128 + n];
        float v1 = W[(size_t)(c + 2 * j + 1) * 128 + n];
        float h0 = __bfloat162float(__float2bfloat16(v0));
        float h1 = __bfloat162float(__float2bfloat16(v1));
        hi[j] = packbf(v0, v1);
        lo[j] = packbf(v0 - h0, v1 - h1);
    }
    *(uint4*)&g_Wb[l][0][n * BROW + c] = make_uint4(hi[0], hi[1], hi[2], hi[3]);
    *(uint4*)&g_Wb[l][1][n * BROW + c] = make_uint4(lo[0], lo[1], lo[2], lo[3]);
}

// ===================== mma.sync GEMM: M = (Hin @ W) * dinv[row] =====================
// CTA: 256 threads (8 warps), tile 128(M)x128(N), K=128.
// SMEM (halves, rows padded to BROW=136): Ah | Al | Bh | Bl, each 128*136.
// Split bf16: acc = Ah*Bh + Ah*Bl + Al*Bh (fp32 accum via mma.sync m16n8k16).
#define TILE_H (128 * BROW)

__global__ void __launch_bounds__(256, 1) k_gemm_mma(const float* __restrict__ xin,
                                                     int layer, int N, int useH) {
    extern __shared__ unsigned short sm[];
    const float* __restrict__ Hin = useH ? (const float*)g_H : xin;

    int tid  = threadIdx.x;
    int lane = tid & 31;
    int wid  = tid >> 5;
    int row0 = blockIdx.x * 128;

    unsigned short* Ah = sm;
    unsigned short* Al = sm + TILE_H;
    unsigned short* Bh = sm + 2 * TILE_H;
    unsigned short* Bl = sm + 3 * TILE_H;

    // ---- stage A: fp32 -> bf16 hi/lo ----
#pragma unroll
    for (int i = 0; i < 8; i++) {
        int j = tid + i * 256;           // 0..2047, each handles 8 floats
        int r = j >> 4;
        int c = (j & 15) << 3;
        float v[8];
        if (row0 + r < N) {
            float4 a = *(const float4*)(Hin + (size_t)(row0 + r) * 128 + c);
            float4 b = *(const float4*)(Hin + (size_t)(row0 + r) * 128 + c + 4);
            v[0] = a.x; v[1] = a.y; v[2] = a.z; v[3] = a.w;
            v[4] = b.x; v[5] = b.y; v[6] = b.z; v[7] = b.w;
        } else {
#pragma unroll
            for (int q = 0; q < 8; q++) v[q] = 0.f;
        }
        uint32_t hi[4], lo[4];
#pragma unroll
        for (int q = 0; q < 4; q++) {
            float x0 = v[2 * q], x1 = v[2 * q + 1];
            float h0 = __bfloat162float(__float2bfloat16(x0));
            float h1 = __bfloat162float(__float2bfloat16(x1));
            hi[q] = packbf(x0, x1);
            lo[q] = packbf(x0 - h0, x1 - h1);
        }
        *(uint4*)&Ah[r * BROW + c] = make_uint4(hi[0], hi[1], hi[2], hi[3]);
        *(uint4*)&Al[r * BROW + c] = make_uint4(lo[0], lo[1], lo[2], lo[3]);
    }

    // ---- copy W images (layout-identical) ----
    {
        const uint4* wh = (const uint4*)g_Wb[layer][0];
        const uint4* wl = (const uint4*)g_Wb[layer][1];
        uint4* bh = (uint4*)Bh;
        uint4* bl = (uint4*)Bl;
        for (int j = tid; j < (TILE_H / 8); j += 256) {   // 2176 uint4
            bh[j] = wh[j];
            bl[j] = wl[j];
        }
    }
    __syncthreads();

    // warp tile: 32 rows x 64 cols
    int wm = wid & 3;            // 4 m-groups
    int wn = wid >> 2;           // 2 n-groups
    int m0 = wm * 32;
    int n0 = wn * 64;
    int gid = lane >> 2;         // 0..7
    int tig = lane & 3;          // 0..3

    float acc[2][8][4];
#pragma unroll
    for (int mf = 0; mf < 2; mf++)
#pragma unroll
        for (int nf = 0; nf < 8; nf++)
#pragma unroll
            for (int q = 0; q < 4; q++) acc[mf][nf][q] = 0.f;

    for (int s = 0; s < 3; s++) {
        const unsigned short* Asel = (s == 2) ? Al : Ah;
        const unsigned short* Bsel = (s == 1) ? Bl : Bh;
#pragma unroll
        for (int k = 0; k < 8; k++) {
            int k0 = k * 16;
            // A fragments (m16n8k16 row-major mapping), conflict-free LDS32
            uint32_t a[2][4];
#pragma unroll
            for (int mf = 0; mf < 2; mf++) {
                int rr = m0 + mf * 16;
                a[mf][0] = *(const uint32_t*)&Asel[(rr + gid)     * BROW + k0 + tig * 2];
                a[mf][1] = *(const uint32_t*)&Asel[(rr + gid + 8) * BROW + k0 + tig * 2];
                a[mf][2] = *(const uint32_t*)&Asel[(rr + gid)     * BROW + k0 + 8 + tig * 2];
                a[mf][3] = *(const uint32_t*)&Asel[(rr + gid + 8) * BROW + k0 + 8 + tig * 2];
            }
            // B fragments (col-major k16xn8 mapping)
            uint32_t b[8][2];
#pragma unroll
            for (int nf = 0; nf < 8; nf++) {
                int n = n0 + nf * 8 + gid;
                b[nf][0] = *(const uint32_t*)&Bsel[n * BROW + k0 + tig * 2];
                b[nf][1] = *(const uint32_t*)&Bsel[n * BROW + k0 + 8 + tig * 2];
            }
#pragma unroll
            for (int mf = 0; mf < 2; mf++)
#pragma unroll
                for (int nf = 0; nf < 8; nf++) {
                    asm volatile(
                        "mma.sync.aligned.m16n8k16.row.col.f32.bf16.bf16.f32 "
                        "{%0,%1,%2,%3}, {%4,%5,%6,%7}, {%8,%9}, {%0,%1,%2,%3};"
                        : "+f"(acc[mf][nf][0]), "+f"(acc[mf][nf][1]),
                          "+f"(acc[mf][nf][2]), "+f"(acc[mf][nf][3])
                        : "r"(a[mf][0]), "r"(a[mf][1]), "r"(a[mf][2]), "r"(a[mf][3]),
                          "r"(b[nf][0]), "r"(b[nf][1]));
                }
        }
    }

    // ---- epilogue: D -> g_M scaled by dinv[row] ----
#pragma unroll
    for (int mf = 0; mf < 2; mf++) {
        int r1 = row0 + m0 + mf * 16 + gid;
        int r2 = r1 + 8;
        float dv1 = (r1 < N) ? g_dinv[r1] : 0.f;
        float dv2 = (r2 < N) ? g_dinv[r2] : 0.f;
#pragma unroll
        for (int nf = 0; nf < 8; nf++) {
            int c = n0 + nf * 8 + tig * 2;
            if (r1 < N)
                *(float2*)(g_M + (size_t)r1 * 128 + c) =
                    make_float2(acc[mf][nf][0] * dv1, acc[mf][nf][1] * dv1);
            if (r2 < N)
                *(float2*)(g_M + (size_t)r2 * 128 + c) =
                    make_float2(acc[mf][nf][2] * dv2, acc[mf][nf][3] * dv2);
        }
    }
}

// ===================== gather aggregation + bias + relu =====================
// H[d] = relu( dinv[d] * ( M[d] + sum_{e: dst=d} M[src_e] ) + b )
__global__ void __launch_bounds__(256) k_gather(const float* __restrict__ b, int N) {
    int w = (blockIdx.x * 256 + threadIdx.x) >> 5;
    if (w >= N) return;
    int lane = threadIdx.x & 31;

    int s0 = g_rptr[w], s1 = g_rptr[w + 1];
    float dv = g_dinv[w];
    const float4* M4 = (const float4*)g_M;

    float4 acc = M4[(size_t)w * 32 + lane];   // self-loop message (pre-scaled by dinv[w])

    int e = s0;
    for (; e + 3 < s1; e += 4) {
        int sa = g_col[e], sb = g_col[e + 1], sc = g_col[e + 2], sd = g_col[e + 3];
        float4 va = M4[(size_t)sa * 32 + lane];
        float4 vb = M4[(size_t)sb * 32 + lane];
        float4 vc = M4[(size_t)sc * 32 + lane];
        float4 vd = M4[(size_t)sd * 32 + lane];
        acc.x += va.x + vb.x + vc.x + vd.x;
        acc.y += va.y + vb.y + vc.y + vd.y;
        acc.z += va.z + vb.z + vc.z + vd.z;
        acc.w += va.w + vb.w + vc.w + vd.w;
    }
    for (; e < s1; e++) {
        int s = g_col[e];
        float4 v = M4[(size_t)s * 32 + lane];
        acc.x += v.x; acc.y += v.y; acc.z += v.z; acc.w += v.w;
    }

    float4 bb = ((const float4*)b)[lane];
    float4 o;
    o.x = fmaxf(acc.x * dv + bb.x, 0.f);
    o.y = fmaxf(acc.y * dv + bb.y, 0.f);
    o.z = fmaxf(acc.z * dv + bb.z, 0.f);
    o.w = fmaxf(acc.w * dv + bb.w, 0.f);
    ((float4*)g_H)[(size_t)w * 32 + lane] = o;
}

// ===================== fused pooling + output linear =====================
__global__ void __launch_bounds__(128) k_pool_out(const float* __restrict__ out_w,
                                                  const float* __restrict__ out_b,
                                                  float* __restrict__ out, int N) {
    int g = blockIdx.x;    // 256 graphs
    int d = threadIdx.x;   // 128 dims

    int lo, hi;
    { int a = 0, b = N; while (a < b) { int m = (a + b) >> 1; if (g_batch[m] < g) a = m + 1; else b = m; } lo = a; }
    { int a = lo, b = N; while (a < b) { int m = (a + b) >> 1; if (g_batch[m] < g + 1) a = m + 1; else b = m; } hi = a; }

    float s = 0.f, mx = 0.f;   // relu output >= 0: max init 0 matches segment_max for non-empty segments
    for (int n = lo; n < hi; n++) {
        float v = g_H[(size_t)n * 128 + d];
        s += v;
        mx = fmaxf(mx, v);
    }
    float cnt  = fmaxf((float)(hi - lo), 1.f);
    float mean = s / cnt;

    __shared__ float sp[128][10];
#pragma unroll
    for (int j = 0; j < 10; j++)
        sp[d][j] = mx * out_w[d * 10 + j]
                 + mean * out_w[(128 + d) * 10 + j]
                 + s * out_w[(256 + d) * 10 + j];
    __syncthreads();

    if (d < 10) {
        float r = 0.f;
        for (int i = 0; i < 128; i++) r += sp[i][d];
        out[g * 10 + d] = r + out_b[d];
    }
}

// ===================== launch =====================
extern "C" void kernel_launch(void* const* d_in, const int* in_sizes, int n_in,
                              void* d_out, int out_size) {
    const float* x      = (const float*)d_in[0];
    const void*  edge   = d_in[1];
    const void*  batch  = d_in[2];
    const float* conv_w = (const float*)d_in[3];
    const float* conv_b = (const float*)d_in[4];
    const float* out_w  = (const float*)d_in[5];
    const float* out_b  = (const float*)d_in[6];
    float*       out    = (float*)d_out;

    int N = in_sizes[0] / 128;
    int E = in_sizes[1] / 2;

    const int SMEM_BYTES = 4 * TILE_H * 2;   // 139264
    static bool attr_done = false;
    if (!attr_done) {
        cudaFuncSetAttribute(k_gemm_mma, cudaFuncAttributeMaxDynamicSharedMemorySize, SMEM_BYTES);
        attr_done = true;
    }

    k_detect<<<1, 1>>>(edge, E);
    k_cvt_edge<<<(E + 255) / 256, 256>>>(edge, E);
    k_cvt_batch<<<(N + 255) / 256, 256>>>(batch, N);

    k_zero<<<(N + 255) / 256, 256>>>(N);
    k_deg<<<(E + 255) / 256, 256>>>(E, N);
    k_dinv<<<(N + 255) / 256, 256>>>(N);
    k_scan<<<1, 1024>>>(N);
    k_fill<<<(E + 255) / 256, 256>>>(E, N);

    k_wconv<<<dim3(16, 3), 128>>>(conv_w);

    int tiles = (N + 127) / 128;
    for (int l = 0; l < 3; l++) {
        k_gemm_mma<<<tiles, 256, SMEM_BYTES>>>(x, l, N, l > 0 ? 1 : 0);
        k_gather<<<(N * 32 + 255) / 256, 256>>>(conv_b + l * 128, N);
    }

    k_pool_out<<<256, 128>>>(out_w, out_b, out, N);
}